// round 10
// baseline (speedup 1.0000x reference)
#include <cuda_runtime.h>
#include <math.h>
#include <stdint.h>

#define BATCH 4
#define SEQ   2048
#define CDIM  1024
#define HD    128
#define QKN   256
#define SCALE_F 0.08838834764831845f

// attention tiling (R7 measured-best attn)
#define BQA 32
#define BKA 64
#define NQTA (SEQ/BQA)
#define KSS 132
#define VSS 136
#define PSS 68
#define KS_TILE (BKA*KSS)
#define ATT_F (4*KS_TILE + BKA*VSS + 2*BQA*PSS + 256)
#define ATT_SMEM (ATT_F*4)

// gemm: 128 x N tiles, Kc=16, 512 threads, dynamic smem
#define AST 20
#define GEMM_AF (2*128*AST)              // 5120 floats
#define GEMM_SMEM ((GEMM_AF + 2*16*264)*4)   // 54272 B

// ---------------- scratch ----------------------------------------------------
__device__ __align__(16) float g_Q[BATCH*SEQ*QKN];   // pre-scaled, tf32-rounded
__device__ __align__(16) float g_K[BATCH*SEQ*QKN];   // tf32-rounded
__device__ __align__(16) float g_V[BATCH*SEQ*HD];    // tf32-rounded

// ---------------- helpers ----------------------------------------------------
__device__ __forceinline__ uint32_t tf32u(float x) {
  uint32_t y; asm("cvt.rna.tf32.f32 %0, %1;" : "=r"(y) : "f"(x)); return y;
}
__device__ __forceinline__ float tf32f(float x) { return __uint_as_float(tf32u(x)); }

__device__ __forceinline__ void mma8(float& c0, float& c1, float& c2, float& c3,
                                     uint32_t a0, uint32_t a1, uint32_t a2, uint32_t a3,
                                     uint32_t b0, uint32_t b1) {
  asm volatile(
    "mma.sync.aligned.m16n8k8.row.col.f32.tf32.tf32.f32 "
    "{%0,%1,%2,%3}, {%4,%5,%6,%7}, {%8,%9}, {%0,%1,%2,%3};\n"
    : "+f"(c0), "+f"(c1), "+f"(c2), "+f"(c3)
    : "r"(a0), "r"(a1), "r"(a2), "r"(a3), "r"(b0), "r"(b1));
}

__device__ __forceinline__ void cpa16(uint32_t dst, const void* src) {
  asm volatile("cp.async.cg.shared.global [%0], [%1], 16;" :: "r"(dst), "l"(src));
}
#define CP_COMMIT() asm volatile("cp.async.commit_group;" ::: "memory")

// ---------------- wide projection GEMM body -----------------------------------
// Block tile 128 x N (full width), Kc=16, 512 threads = 16 warps (4m x 4n),
// warp tile 32 x (N/4). Double-buffered register-staged loads, tf32 in smem.
template<int N>
__device__ __forceinline__ void gemm_body(const float* __restrict__ A,
                                          const float* __restrict__ W,
                                          float* __restrict__ C,
                                          int mBase, float scale, float* gsm) {
  constexpr int NT  = N/32;      // n-tiles per warp (8 or 4)
  constexpr int BST = N + 8;     // ≡8 mod 32
  float* Asm = gsm;              // [2][128*AST]
  float* Bsm = gsm + GEMM_AF;    // [2][16*BST]

  int tid = threadIdx.x, lane = tid & 31, wid = tid >> 5;
  int wm = wid & 3, wn = wid >> 2;
  int gID = lane >> 2, tig = lane & 3;
  int arow = tid >> 2, ac4 = (tid & 3) << 2;

  float4 ra, rb[2];
  auto ldt = [&](int it) {
    int k0 = it << 4;
    ra = *(const float4*)(A + (size_t)(mBase + arow)*CDIM + k0 + ac4);
    #pragma unroll
    for (int p = 0; p < N/128; ++p) {
      int idx = tid + p*512;
      int br = idx / (N/4), bc4 = (idx % (N/4)) << 2;
      rb[p] = *(const float4*)(W + (size_t)(k0 + br)*N + bc4);
    }
  };
  auto stt = [&](int buf) {
    float* Ab = Asm + buf*(128*AST);
    float* Bb = Bsm + buf*(16*BST);
    float* d = Ab + arow*AST + ac4;
    d[0]=tf32f(ra.x); d[1]=tf32f(ra.y); d[2]=tf32f(ra.z); d[3]=tf32f(ra.w);
    #pragma unroll
    for (int p = 0; p < N/128; ++p) {
      int idx = idx = tid + p*512;
      int br = idx / (N/4), bc4 = (idx % (N/4)) << 2;
      float* e = Bb + br*BST + bc4;
      e[0]=tf32f(rb[p].x); e[1]=tf32f(rb[p].y); e[2]=tf32f(rb[p].z); e[3]=tf32f(rb[p].w);
    }
  };

  float c[2][NT][4] = {};
  ldt(0); stt(0); __syncthreads();
  for (int it = 0; it < 64; ++it) {
    int cb = it & 1;
    const float* Ab = Asm + cb*(128*AST);
    const float* Bb = Bsm + cb*(16*BST);
    if (it < 63) ldt(it + 1);
    #pragma unroll
    for (int ks = 0; ks < 2; ++ks) {
      uint32_t a[2][4], bf[NT][2];
      #pragma unroll
      for (int mt = 0; mt < 2; ++mt) {
        const float* ap = Ab + (wm*32 + mt*16 + gID)*AST + ks*8;
        a[mt][0] = __float_as_uint(ap[tig]);
        a[mt][1] = __float_as_uint(ap[8*AST + tig]);
        a[mt][2] = __float_as_uint(ap[tig + 4]);
        a[mt][3] = __float_as_uint(ap[8*AST + tig + 4]);
      }
      #pragma unroll
      for (int nt = 0; nt < NT; ++nt) {
        int col = wn*(N/4) + nt*8 + gID;
        bf[nt][0] = __float_as_uint(Bb[(ks*8 + tig)*BST + col]);
        bf[nt][1] = __float_as_uint(Bb[(ks*8 + tig + 4)*BST + col]);
      }
      #pragma unroll
      for (int mt = 0; mt < 2; ++mt)
        #pragma unroll
        for (int nt = 0; nt < NT; ++nt)
          mma8(c[mt][nt][0], c[mt][nt][1], c[mt][nt][2], c[mt][nt][3],
               a[mt][0], a[mt][1], a[mt][2], a[mt][3], bf[nt][0], bf[nt][1]);
    }
    if (it < 63) { stt(cb ^ 1); __syncthreads(); }
  }
  #pragma unroll
  for (int mt = 0; mt < 2; ++mt)
    #pragma unroll
    for (int nt = 0; nt < NT; ++nt) {
      int r0 = mBase + wm*32 + mt*16 + gID;
      int col = wn*(N/4) + nt*8 + 2*tig;
      float* f = c[mt][nt];
      *(float2*)(C + (size_t)r0*N + col)     = make_float2(tf32f(f[0]*scale), tf32f(f[1]*scale));
      *(float2*)(C + (size_t)(r0+8)*N + col) = make_float2(tf32f(f[2]*scale), tf32f(f[3]*scale));
    }
}

__global__ __launch_bounds__(512) void gemm_all(
    const float* __restrict__ q, const float* __restrict__ k, const float* __restrict__ v,
    const float* __restrict__ Wq, const float* __restrict__ Wk, const float* __restrict__ Wv) {
  extern __shared__ float gsm[];
  int bid = blockIdx.x;
  if (bid < 64)        gemm_body<256>(q, Wq, g_Q, bid << 7,        SCALE_F, gsm);
  else if (bid < 128)  gemm_body<256>(k, Wk, g_K, (bid - 64) << 7, 1.f,     gsm);
  else                 gemm_body<128>(v, Wv, g_V, (bid - 128) << 7, 1.f,    gsm);
}

// ---------------- fused differential flash attention (R7 measured-best) ------
// 256 threads = 8 warps: stream=wid&1 (4 warps/stream), within stream:
// wm=(wid>>1)&1 -> rows [wm*16,+16), wgrp=wid>>2 -> S cols [wgrp*32,+32),
// O cols [wgrp*64,+64). K double-buffered via cp.async; V single-buffer.
__global__ __launch_bounds__(256, 1) void attn_tc(
    float* __restrict__ out,
    const float* __restrict__ lq1, const float* __restrict__ lk1,
    const float* __restrict__ lq2, const float* __restrict__ lk2) {
  extern __shared__ float sm[];
  float* Ks  = sm;                        // [db][stream][64][KSS]
  float* Vs  = Ks + 4*KS_TILE;            // [64][VSS]
  float* Ps  = Vs + BKA*VSS;              // [stream][32][PSS]
  float* red = Ps + 2*BQA*PSS;            // [stream][128]

  int bid = blockIdx.x;
  int b, qt;
  if (bid < 148) { b = bid & 3; qt = (NQTA-1) - (bid >> 2); }
  else           { int r = bid - 148; b = r & 3; qt = r >> 2; }
  int q0 = qt * BQA;

  int tid = threadIdx.x, lane = tid & 31, wid = tid >> 5;
  int stream = wid & 1, wsub = wid >> 1;
  int wm = wsub & 1, wgrp = wsub >> 1;
  int mrow = wm*16, scol = wgrp*32, ocol = wgrp*64;
  int gID = lane >> 2, tig = lane & 3;
  int kt_end = min((q0 + BQA) >> 6, (SEQ-1) >> 6);

  uint32_t KsU = (uint32_t)__cvta_generic_to_shared(Ks);
  uint32_t VsU = (uint32_t)__cvta_generic_to_shared(Vs);

  auto issueK = [&](int ktile, int dbuf) {
    int j0 = ktile * BKA;
    #pragma unroll
    for (int i = 0; i < 16; ++i) {
      int idx = tid + i*256;
      int st  = idx >> 11;
      int rem = idx & 2047;
      int j = rem >> 5, d4 = rem & 31;
      const float* src = g_K + ((size_t)(b*SEQ + j0 + j))*QKN + st*HD + (d4 << 2);
      uint32_t dst = KsU + (((dbuf*2 + st)*KS_TILE) + j*KSS + (d4 << 2))*4u;
      cpa16(dst, src);
    }
  };
  auto issueV = [&](int ktile) {
    int j0 = ktile * BKA;
    #pragma unroll
    for (int i = 0; i < 8; ++i) {
      int idx = tid + i*256;
      int j = idx >> 5, d4 = idx & 31;
      const float* src = g_V + ((size_t)(b*SEQ + j0 + j))*HD + (d4 << 2);
      uint32_t dst = VsU + (j*VSS + (d4 << 2))*4u;
      cpa16(dst, src);
    }
  };

  uint32_t qf[16][4];
  {
    const float* qb = g_Q + ((size_t)(b*SEQ + q0 + mrow))*QKN + stream*HD;
    #pragma unroll
    for (int ks = 0; ks < 16; ++ks) {
      qf[ks][0] = __float_as_uint(qb[(size_t)gID*QKN     + ks*8 + tig]);
      qf[ks][1] = __float_as_uint(qb[(size_t)(gID+8)*QKN + ks*8 + tig]);
      qf[ks][2] = __float_as_uint(qb[(size_t)gID*QKN     + ks*8 + tig + 4]);
      qf[ks][3] = __float_as_uint(qb[(size_t)(gID+8)*QKN + ks*8 + tig + 4]);
    }
  }

  float O[8][4] = {};
  float m_lo = -1e30f, m_hi = -1e30f, l_lo = 0.f, l_hi = 0.f;

  issueK(0, 0); CP_COMMIT();

  for (int kt = 0; kt <= kt_end; ++kt) {
    int db = kt & 1;
    __syncthreads();
    issueV(kt); CP_COMMIT();
    bool more = (kt < kt_end);
    if (more) { issueK(kt + 1, db ^ 1); CP_COMMIT(); }
    if (more) asm volatile("cp.async.wait_group 1;" ::: "memory");
    else      asm volatile("cp.async.wait_group 0;" ::: "memory");
    __syncthreads();

    const float* Kb = Ks + (db*2 + stream)*KS_TILE;
    float S[4][4] = {};
    #pragma unroll
    for (int ks = 0; ks < 16; ++ks) {
      #pragma unroll
      for (int nt = 0; nt < 4; ++nt) {
        int jl = scol + nt*8 + gID;
        uint32_t b0 = __float_as_uint(Kb[jl*KSS + ks*8 + tig]);
        uint32_t b1 = __float_as_uint(Kb[jl*KSS + ks*8 + tig + 4]);
        mma8(S[nt][0], S[nt][1], S[nt][2], S[nt][3],
             qf[ks][0], qf[ks][1], qf[ks][2], qf[ks][3], b0, b1);
      }
    }

    int j0k = kt * BKA;
    int r_lo = q0 + mrow + gID, r_hi = r_lo + 8;
    float mx0 = -1e30f, mx1 = -1e30f;
    #pragma unroll
    for (int nt = 0; nt < 4; ++nt) {
      int jb = j0k + scol + nt*8 + 2*tig;
      S[nt][0] = (jb     <= r_lo + 1) ? S[nt][0] : -1e30f;
      S[nt][1] = (jb + 1 <= r_lo + 1) ? S[nt][1] : -1e30f;
      S[nt][2] = (jb     <= r_hi + 1) ? S[nt][2] : -1e30f;
      S[nt][3] = (jb + 1 <= r_hi + 1) ? S[nt][3] : -1e30f;
      mx0 = fmaxf(mx0, fmaxf(S[nt][0], S[nt][1]));
      mx1 = fmaxf(mx1, fmaxf(S[nt][2], S[nt][3]));
    }
    mx0 = fmaxf(mx0, __shfl_xor_sync(0xffffffffu, mx0, 1));
    mx0 = fmaxf(mx0, __shfl_xor_sync(0xffffffffu, mx0, 2));
    mx1 = fmaxf(mx1, __shfl_xor_sync(0xffffffffu, mx1, 1));
    mx1 = fmaxf(mx1, __shfl_xor_sync(0xffffffffu, mx1, 2));
    float* redS = red + stream*128;
    if (tig == 0) {
      redS[wgrp*32 + mrow + gID]     = mx0;
      redS[wgrp*32 + mrow + gID + 8] = mx1;
    }
    __syncthreads();
    mx0 = fmaxf(mx0, redS[(wgrp^1)*32 + mrow + gID]);
    mx1 = fmaxf(mx1, redS[(wgrp^1)*32 + mrow + gID + 8]);
    float mn0 = fmaxf(m_lo, mx0), mn1 = fmaxf(m_hi, mx1);
    float al0 = __expf(m_lo - mn0), al1 = __expf(m_hi - mn1);
    m_lo = mn0; m_hi = mn1;

    float* PsS = Ps + stream*BQA*PSS;
    float s0 = 0.f, s1 = 0.f;
    #pragma unroll
    for (int nt = 0; nt < 4; ++nt) {
      float p00 = __expf(S[nt][0] - mn0), p01 = __expf(S[nt][1] - mn0);
      float p10 = __expf(S[nt][2] - mn1), p11 = __expf(S[nt][3] - mn1);
      s0 += p00 + p01; s1 += p10 + p11;
      int cl = scol + nt*8 + 2*tig;
      *(float2*)(PsS + (mrow + gID)*PSS + cl)     = make_float2(tf32f(p00), tf32f(p01));
      *(float2*)(PsS + (mrow + gID + 8)*PSS + cl) = make_float2(tf32f(p10), tf32f(p11));
    }
    s0 += __shfl_xor_sync(0xffffffffu, s0, 1); s0 += __shfl_xor_sync(0xffffffffu, s0, 2);
    s1 += __shfl_xor_sync(0xffffffffu, s1, 1); s1 += __shfl_xor_sync(0xffffffffu, s1, 2);
    if (tig == 0) {
      redS[64 + wgrp*32 + mrow + gID]     = s0;
      redS[64 + wgrp*32 + mrow + gID + 8] = s1;
    }
    __syncthreads();
    s0 += redS[64 + (wgrp^1)*32 + mrow + gID];
    s1 += redS[64 + (wgrp^1)*32 + mrow + gID + 8];
    l_lo = l_lo*al0 + s0;
    l_hi = l_hi*al1 + s1;
    #pragma unroll
    for (int nt = 0; nt < 8; ++nt) {
      O[nt][0] *= al0; O[nt][1] *= al0; O[nt][2] *= al1; O[nt][3] *= al1;
    }

    #pragma unroll
    for (int kk = 0; kk < 8; ++kk) {
      const float* pr0 = PsS + (mrow + gID)*PSS + kk*8;
      const float* pr1 = PsS + (mrow + gID + 8)*PSS + kk*8;
      uint32_t pa0 = __float_as_uint(pr0[tig]);
      uint32_t pa1 = __float_as_uint(pr1[tig]);
      uint32_t pa2 = __float_as_uint(pr0[tig + 4]);
      uint32_t pa3 = __float_as_uint(pr1[tig + 4]);
      #pragma unroll
      for (int nt = 0; nt < 8; ++nt) {
        int col = ocol + nt*8 + gID;
        uint32_t b0 = __float_as_uint(Vs[(kk*8 + tig)*VSS + col]);
        uint32_t b1 = __float_as_uint(Vs[(kk*8 + tig + 4)*VSS + col]);
        mma8(O[nt][0], O[nt][1], O[nt][2], O[nt][3], pa0, pa1, pa2, pa3, b0, b1);
      }
    }
  } // kt

  float il0 = 1.f / l_lo, il1 = 1.f / l_hi;
  __syncthreads();
  if (stream == 1) {
    float d1 = 0.f, d2 = 0.f;
    #pragma unroll
    for (int i = 0; i < 4; ++i) {
      int ix = lane + i*32;
      d1 += lq1[ix]*lk1[ix];
      d2 += lq2[ix]*lk2[ix];
    }
    #pragma unroll
    for (int off = 16; off; off >>= 1) {
      d1 += __shfl_xor_sync(0xffffffffu, d1, off);
      d2 += __shfl_xor_sync(0xffffffffu, d2, off);
    }
    float lbd = __expf(d1) - __expf(d2) + 0.8f;
    #pragma unroll
    for (int nt = 0; nt < 8; ++nt) {
      int col = ocol + nt*8 + 2*tig;
      *(float2*)(Ps + (mrow + gID)*132 + col) =
          make_float2(lbd*O[nt][0]*il0, lbd*O[nt][1]*il0);
      *(float2*)(Ps + (mrow + gID + 8)*132 + col) =
          make_float2(lbd*O[nt][2]*il1, lbd*O[nt][3]*il1);
    }
  }
  __syncthreads();
  if (stream == 0) {
    float* ob = out + ((size_t)(b*SEQ + q0 + mrow))*HD;
    #pragma unroll
    for (int nt = 0; nt < 8; ++nt) {
      int col = ocol + nt*8 + 2*tig;
      float2 c0 = *(float2*)(Ps + (mrow + gID)*132 + col);
      float2 c1 = *(float2*)(Ps + (mrow + gID + 8)*132 + col);
      *(float2*)(ob + (size_t)gID*HD + col) =
          make_float2(O[nt][0]*il0 - c0.x, O[nt][1]*il0 - c0.y);
      *(float2*)(ob + (size_t)(gID+8)*HD + col) =
          make_float2(O[nt][2]*il1 - c1.x, O[nt][3]*il1 - c1.y);
    }
  }
}

// ---------------- launch ------------------------------------------------------
extern "C" void kernel_launch(void* const* d_in, const int* in_sizes, int n_in,
                              void* d_out, int out_size) {
  const float* q   = (const float*)d_in[0];
  const float* k   = (const float*)d_in[1];
  const float* v   = (const float*)d_in[2];
  const float* Wq  = (const float*)d_in[3];
  const float* Wk  = (const float*)d_in[4];
  const float* Wv  = (const float*)d_in[5];
  const float* lq1 = (const float*)d_in[6];
  const float* lk1 = (const float*)d_in[7];
  const float* lq2 = (const float*)d_in[8];
  const float* lk2 = (const float*)d_in[9];
  float* out = (float*)d_out;

  cudaFuncSetAttribute(gemm_all, cudaFuncAttributeMaxDynamicSharedMemorySize, GEMM_SMEM);
  cudaFuncSetAttribute(attn_tc, cudaFuncAttributeMaxDynamicSharedMemorySize, ATT_SMEM);

  gemm_all<<<192, 512, GEMM_SMEM>>>(q, k, v, Wq, Wk, Wv);
  attn_tc<<<4*NQTA, 256, ATT_SMEM>>>(out, lq1, lk1, lq2, lk2);
}